// round 1
// baseline (speedup 1.0000x reference)
#include <cuda_runtime.h>

typedef unsigned long long ull;

#define Bn 128
#define Tn 512
#define Dn 32
#define Nn 64

// scratch for cross-d reduction (no allocations allowed)
__device__ float g_mu[Bn * Dn];
__device__ float g_tb[Bn * Dn];

static __device__ __forceinline__ ull pack2(float lo, float hi) {
    ull r; asm("mov.b64 %0, {%1, %2};" : "=l"(r) : "f"(lo), "f"(hi)); return r;
}
static __device__ __forceinline__ void unpack2(ull v, float &lo, float &hi) {
    asm("mov.b64 {%0, %1}, %2;" : "=f"(lo), "=f"(hi) : "l"(v));
}
// packed 2xfp32 FMA (Blackwell): d = a*b + c
static __device__ __forceinline__ ull fma2(ull a, ull b, ull c) {
    ull d; asm("fma.rn.f32x2 %0, %1, %2, %3;" : "=l"(d) : "l"(a), "l"(b), "l"(c)); return d;
}
static __device__ __forceinline__ float sigf(float x) {
    return __fdividef(1.f, 1.f + __expf(-x));
}
static __device__ __forceinline__ float tanhf_fast(float x) {
    float ax = fabsf(x);
    float e  = __expf(-2.f * ax);
    float r  = __fdividef(1.f - e, 1.f + e);
    return copysignf(r, x);
}

// smem h layout: [2 buffers][Nn rows][36 cols (32 batches + pad)]
#define HROW 36
#define HBUF (Nn * HROW)
#define SMEM_BYTES (4 * Nn * Nn * 4 + 2 * HBUF * 4)

__global__ void __launch_bounds__(256, 1)
imv_lstm_kernel(const float* __restrict__ x,
                const float* __restrict__ Uj, const float* __restrict__ Ui,
                const float* __restrict__ Uf, const float* __restrict__ Uo,
                const float* __restrict__ Wj, const float* __restrict__ Wi,
                const float* __restrict__ Wf, const float* __restrict__ Wo,
                const float* __restrict__ bj, const float* __restrict__ bi,
                const float* __restrict__ bf, const float* __restrict__ bo,
                const float* __restrict__ Fa, const float* __restrict__ Fab,
                const float* __restrict__ Fbw, const float* __restrict__ Fbb,
                const float* __restrict__ Phiw, const float* __restrict__ Phib)
{
    extern __shared__ float sm[];
    float* Wsm = sm;                    // [4][64][64]
    float* hsm = sm + 4 * Nn * Nn;      // [2][64][36]

    const int tid = threadIdx.x;
    const int np  = tid & 31;           // n-pair index: n = {2np, 2np+1}
    const int w   = tid >> 5;           // warp id 0..7 -> 4 batches each
    const int d   = blockIdx.x & 31;
    const int bq  = blockIdx.x >> 5;    // batch quarter 0..3
    const int b0  = bq * 32 + w * 4;
    const int n0  = 2 * np;

    // --- stage W[d] (4 gates) into smem ---
    {
        const float* Wg[4] = { Wj + d * Nn * Nn, Wi + d * Nn * Nn,
                               Wf + d * Nn * Nn, Wo + d * Nn * Nn };
#pragma unroll
        for (int g = 0; g < 4; g++) {
            const float4* src = reinterpret_cast<const float4*>(Wg[g]);
            float4* dst = reinterpret_cast<float4*>(Wsm + g * Nn * Nn);
            for (int i = tid; i < (Nn * Nn) / 4; i += 256) dst[i] = src[i];
        }
        for (int i = tid; i < 2 * HBUF; i += 256) hsm[i] = 0.f;
    }

    // --- per-thread constants (n0, n0+1 of this d) ---
    const int dn = d * Nn + n0;
    const float ujx = Uj[dn], ujy = Uj[dn + 1];
    const float uix = Ui[dn], uiy = Ui[dn + 1];
    const float ufx = Uf[dn], ufy = Uf[dn + 1];
    const float uox = Uo[dn], uoy = Uo[dn + 1];
    const float bjx = bj[dn], bjy = bj[dn + 1];
    const float bix = bi[dn], biy = bi[dn + 1];
    const float bfx = bf[dn], bfy = bf[dn + 1];
    const float box_ = bo[dn], boy = bo[dn + 1];
    const float fax = Fa[dn], fay = Fa[dn + 1];
    const float fab = Fab[d];

    // --- per-thread state: 4 batches x n-pair ---
    ull   c2[4]   = {0ull, 0ull, 0ull, 0ull};
    ull   h2[4]   = {0ull, 0ull, 0ull, 0ull};
    ull   gac2[4] = {0ull, 0ull, 0ull, 0ull};
    float suma[4] = {0.f, 0.f, 0.f, 0.f};

    __syncthreads();

    int cur = 0;
    for (int t = 0; t < Tn; t++) {
        // prefetch x (latency hidden by the k-loop)
        float xv[4];
#pragma unroll
        for (int i = 0; i < 4; i++)
            xv[i] = __ldg(&x[(b0 + i) * (Tn * Dn) + t * Dn + d]);

        ull aJ[4] = {0,0,0,0}, aI[4] = {0,0,0,0}, aF[4] = {0,0,0,0}, aO[4] = {0,0,0,0};

        const float* hbase = hsm + cur * HBUF + w * 4;
#pragma unroll 8
        for (int k = 0; k < Nn; k++) {
            const float4 hv = *reinterpret_cast<const float4*>(hbase + k * HROW);
            const ull h0 = pack2(hv.x, hv.x);
            const ull h1 = pack2(hv.y, hv.y);
            const ull hh2 = pack2(hv.z, hv.z);
            const ull h3 = pack2(hv.w, hv.w);
            const float* wrow = Wsm + k * Nn + n0;
            const ull wjv = *reinterpret_cast<const ull*>(wrow);
            const ull wiv = *reinterpret_cast<const ull*>(wrow + Nn * Nn);
            const ull wfv = *reinterpret_cast<const ull*>(wrow + 2 * Nn * Nn);
            const ull wov = *reinterpret_cast<const ull*>(wrow + 3 * Nn * Nn);
            aJ[0] = fma2(wjv, h0, aJ[0]); aJ[1] = fma2(wjv, h1, aJ[1]);
            aJ[2] = fma2(wjv, hh2, aJ[2]); aJ[3] = fma2(wjv, h3, aJ[3]);
            aI[0] = fma2(wiv, h0, aI[0]); aI[1] = fma2(wiv, h1, aI[1]);
            aI[2] = fma2(wiv, hh2, aI[2]); aI[3] = fma2(wiv, h3, aI[3]);
            aF[0] = fma2(wfv, h0, aF[0]); aF[1] = fma2(wfv, h1, aF[1]);
            aF[2] = fma2(wfv, hh2, aF[2]); aF[3] = fma2(wfv, h3, aF[3]);
            aO[0] = fma2(wov, h0, aO[0]); aO[1] = fma2(wov, h1, aO[1]);
            aO[2] = fma2(wov, hh2, aO[2]); aO[3] = fma2(wov, h3, aO[3]);
        }

        const int nxt = cur ^ 1;
        float pa[4];
        float* hw0 = hsm + nxt * HBUF + n0 * HROW + w * 4;       // row n0
        float* hw1 = hsm + nxt * HBUF + (n0 + 1) * HROW + w * 4; // row n0+1
#pragma unroll
        for (int i = 0; i < 4; i++) {
            float jx, jy, ix, iy, fx, fy, ox, oy;
            unpack2(aJ[i], jx, jy); unpack2(aI[i], ix, iy);
            unpack2(aF[i], fx, fy); unpack2(aO[i], ox, oy);
            const float xb = xv[i];
            jx = tanhf_fast(jx + xb * ujx + bjx);
            jy = tanhf_fast(jy + xb * ujy + bjy);
            ix = sigf(ix + xb * uix + bix);
            iy = sigf(iy + xb * uiy + biy);
            fx = sigf(fx + xb * ufx + bfx);
            fy = sigf(fy + xb * ufy + bfy);
            ox = sigf(ox + xb * uox + box_);
            oy = sigf(oy + xb * uoy + boy);
            float cx, cy; unpack2(c2[i], cx, cy);
            cx = cx * fx + ix * jx;
            cy = cy * fy + iy * jy;
            const float hx = ox * tanhf_fast(cx);
            const float hy = oy * tanhf_fast(cy);
            c2[i] = pack2(cx, cy);
            h2[i] = pack2(hx, hy);
            pa[i] = hx * fax + hy * fay;
            hw0[i] = hx;
            hw1[i] = hy;
        }
        // warp-level reduction over all 64 n (full warp = one batch group)
#pragma unroll
        for (int off = 16; off; off >>= 1) {
#pragma unroll
            for (int i = 0; i < 4; i++)
                pa[i] += __shfl_xor_sync(0xffffffffu, pa[i], off);
        }
#pragma unroll
        for (int i = 0; i < 4; i++) {
            const float a = __expf(tanhf_fast(pa[i] + fab));
            suma[i] += a;
            gac2[i] = fma2(pack2(a, a), h2[i], gac2[i]);
        }
        __syncthreads();
        cur = nxt;
    }

    // --- epilogue: g_n = gacc/suma, hg = [g_n, h_T], mu & beta dots ---
    float pm[4], pb[4];
    const float pwx  = Phiw[n0],      pwy  = Phiw[n0 + 1];
    const float pwx2 = Phiw[Nn + n0], pwy2 = Phiw[Nn + n0 + 1];
    const float fwx  = Fbw[n0],       fwy  = Fbw[n0 + 1];
    const float fwx2 = Fbw[Nn + n0],  fwy2 = Fbw[Nn + n0 + 1];
#pragma unroll
    for (int i = 0; i < 4; i++) {
        float gx, gy; unpack2(gac2[i], gx, gy);
        const float inv = __fdividef(1.f, suma[i]);
        gx *= inv; gy *= inv;
        float hx, hy; unpack2(h2[i], hx, hy);
        pm[i] = gx * pwx + gy * pwy + hx * pwx2 + hy * pwy2;
        pb[i] = gx * fwx + gy * fwy + hx * fwx2 + hy * fwy2;
    }
#pragma unroll
    for (int off = 16; off; off >>= 1) {
#pragma unroll
        for (int i = 0; i < 4; i++) {
            pm[i] += __shfl_xor_sync(0xffffffffu, pm[i], off);
            pb[i] += __shfl_xor_sync(0xffffffffu, pb[i], off);
        }
    }
    if (np == 0) {
        const float phib = Phib[0];
        const float fbb  = Fbb[0];
#pragma unroll
        for (int i = 0; i < 4; i++) {
            g_mu[(b0 + i) * Dn + d] = pm[i] + phib;
            g_tb[(b0 + i) * Dn + d] = __expf(tanhf_fast(pb[i] + fbb));
        }
    }
}

__global__ void imv_finalize_kernel(float* __restrict__ out)
{
    const int b = threadIdx.x;
    float s = 0.f, acc = 0.f;
#pragma unroll
    for (int dd = 0; dd < Dn; dd++) {
        const float wgt = g_tb[b * Dn + dd];
        s   += wgt;
        acc += wgt * g_mu[b * Dn + dd];
    }
    out[b] = acc / s;
}

extern "C" void kernel_launch(void* const* d_in, const int* in_sizes, int n_in,
                              void* d_out, int out_size)
{
    (void)in_sizes; (void)n_in; (void)out_size;
    const float* x   = (const float*)d_in[0];
    const float* Uj  = (const float*)d_in[1];
    const float* Ui  = (const float*)d_in[2];
    const float* Uf  = (const float*)d_in[3];
    const float* Uo  = (const float*)d_in[4];
    const float* Wj  = (const float*)d_in[5];
    const float* Wi  = (const float*)d_in[6];
    const float* Wf  = (const float*)d_in[7];
    const float* Wo  = (const float*)d_in[8];
    const float* bj  = (const float*)d_in[9];
    const float* bi  = (const float*)d_in[10];
    const float* bf  = (const float*)d_in[11];
    const float* bo  = (const float*)d_in[12];
    const float* Fa  = (const float*)d_in[13];
    const float* Fab = (const float*)d_in[14];
    const float* Fbw = (const float*)d_in[15];
    const float* Fbb = (const float*)d_in[16];
    const float* Phw = (const float*)d_in[17];
    const float* Phb = (const float*)d_in[18];
    float* out = (float*)d_out;

    static int attr_set = 0;
    if (!attr_set) {
        cudaFuncSetAttribute(imv_lstm_kernel,
                             cudaFuncAttributeMaxDynamicSharedMemorySize,
                             SMEM_BYTES);
        attr_set = 1;
    }

    imv_lstm_kernel<<<Bn / 32 * Dn, 256, SMEM_BYTES>>>(
        x, Uj, Ui, Uf, Uo, Wj, Wi, Wf, Wo, bj, bi, bf, bo,
        Fa, Fab, Fbw, Fbb, Phw, Phb);
    imv_finalize_kernel<<<1, Bn>>>(out);
}